// round 2
// baseline (speedup 1.0000x reference)
#include <cuda_runtime.h>

#define Bb 2
#define Ss 2048
#define Dd 768
#define Pp 16

// ---------------- scratch (device globals; no allocations allowed) ----------
__device__ float g_q[Bb * Ss * Dd];
__device__ float g_k[Bb * Ss * Dd];
__device__ float g_v[Bb * Ss * Dd];
__device__ float g_sc[Bb * Ss * Ss];          // full score matrix, shared by all patches
__device__ float g_m[Bb * Pp * Ss];           // per (b,p,q) running max
__device__ float g_il[Bb * Pp * Ss];          // per (b,p,q) 1/sumexp
__device__ int   g_seg[Bb * Pp];              // decoded patch start indices

// ---------------- robust patch-index decode (int64 vs int32 dtype) ----------
__global__ void decode_idx(const void* __restrict__ raw)
{
    const long long* p64 = (const long long*)raw;
    const int*       p32 = (const int*)raw;
    // validate int64 interpretation: all in [0, Ss), strictly increasing per row
    bool ok64 = true;
    for (int b = 0; b < Bb && ok64; b++) {
        long long prev = -1;
        for (int p = 0; p < Pp; p++) {
            long long v = p64[b * Pp + p];
            if (v < 0 || v >= Ss || v <= prev) { ok64 = false; break; }
            prev = v;
        }
    }
    bool ok32 = true;
    for (int b = 0; b < Bb && ok32; b++) {
        int prev = -1;
        for (int p = 0; p < Pp; p++) {
            int v = p32[b * Pp + p];
            if (v < 0 || v >= Ss || v <= prev) { ok32 = false; break; }
            prev = v;
        }
    }
    for (int i = 0; i < Bb * Pp; i++)
        g_seg[i] = ok64 ? (int)p64[i] : (ok32 ? p32[i] : (int)p64[i]);
}

// ---------------- projection GEMM: out = x @ W + bias -----------------------
// M = B*S = 4096, N = K = 768. 64x64 block tile, BK=16, 256 thr, 4x4 micro.
__global__ void proj_gemm(const float* __restrict__ x, const float* __restrict__ W,
                          const float* __restrict__ bias, float* __restrict__ out)
{
    __shared__ __align__(16) float As[16][65];
    __shared__ __align__(16) float Bs[16][68];
    const int tid = threadIdx.x;
    const int m0 = blockIdx.y * 64;
    const int n0 = blockIdx.x * 64;
    const int arow = tid >> 2, ak4 = (tid & 3) << 2;      // A loader: row 0..63, k-quad
    const int bk   = tid >> 4, bn4 = (tid & 15) << 2;     // B loader: k-row 0..15, n-quad
    const int mr = (tid >> 4) << 2, nr = (tid & 15) << 2; // compute micro-tile origin
    float acc[4][4] = {};
    for (int kt = 0; kt < Dd; kt += 16) {
        float4 av = *(const float4*)&x[(m0 + arow) * Dd + kt + ak4];
        As[ak4 + 0][arow] = av.x; As[ak4 + 1][arow] = av.y;
        As[ak4 + 2][arow] = av.z; As[ak4 + 3][arow] = av.w;
        *(float4*)&Bs[bk][bn4] = *(const float4*)&W[(kt + bk) * Dd + n0 + bn4];
        __syncthreads();
        #pragma unroll
        for (int kk = 0; kk < 16; kk++) {
            float a[4], b[4];
            #pragma unroll
            for (int i = 0; i < 4; i++) a[i] = As[kk][mr + i];
            #pragma unroll
            for (int j = 0; j < 4; j++) b[j] = Bs[kk][nr + j];
            #pragma unroll
            for (int i = 0; i < 4; i++)
                #pragma unroll
                for (int j = 0; j < 4; j++) acc[i][j] += a[i] * b[j];
        }
        __syncthreads();
    }
    #pragma unroll
    for (int i = 0; i < 4; i++)
        #pragma unroll
        for (int j = 0; j < 4; j++)
            out[(m0 + mr + i) * Dd + n0 + nr + j] = acc[i][j] + bias[n0 + nr + j];
}

// ---------------- scores GEMM: sc[b,i,j] = scale * dot(q[b,i,:], k[b,j,:]) ---
__global__ void scores_gemm()
{
    __shared__ float As[16][65];
    __shared__ float Bs[16][65];
    const int b = blockIdx.z;
    const int tid = threadIdx.x;
    const int m0 = blockIdx.y * 64;
    const int n0 = blockIdx.x * 64;
    const int arow = tid >> 2, ak4 = (tid & 3) << 2;
    const int mr = (tid >> 4) << 2, nr = (tid & 15) << 2;
    const float* qb = g_q + b * Ss * Dd;
    const float* kb = g_k + b * Ss * Dd;
    float acc[4][4] = {};
    for (int kt = 0; kt < Dd; kt += 16) {
        float4 av = *(const float4*)&qb[(m0 + arow) * Dd + kt + ak4];
        As[ak4 + 0][arow] = av.x; As[ak4 + 1][arow] = av.y;
        As[ak4 + 2][arow] = av.z; As[ak4 + 3][arow] = av.w;
        float4 bv = *(const float4*)&kb[(n0 + arow) * Dd + kt + ak4];
        Bs[ak4 + 0][arow] = bv.x; Bs[ak4 + 1][arow] = bv.y;
        Bs[ak4 + 2][arow] = bv.z; Bs[ak4 + 3][arow] = bv.w;
        __syncthreads();
        #pragma unroll
        for (int kk = 0; kk < 16; kk++) {
            float a[4], c[4];
            #pragma unroll
            for (int i = 0; i < 4; i++) a[i] = As[kk][mr + i];
            #pragma unroll
            for (int j = 0; j < 4; j++) c[j] = Bs[kk][nr + j];
            #pragma unroll
            for (int i = 0; i < 4; i++)
                #pragma unroll
                for (int j = 0; j < 4; j++) acc[i][j] += a[i] * c[j];
        }
        __syncthreads();
    }
    const float scale = 0.03608439182435161f;  // 1/sqrt(768)
    float* dst = g_sc + (long)b * Ss * Ss;
    #pragma unroll
    for (int i = 0; i < 4; i++)
        #pragma unroll
        for (int j = 0; j < 4; j++)
            dst[(m0 + mr + i) * Ss + n0 + nr + j] = acc[i][j] * scale;
}

// ---------------- softmax stats: per (b,p,q) max & 1/sumexp over segment ----
__global__ void stats_kernel()
{
    const int wid  = (blockIdx.x * blockDim.x + threadIdx.x) >> 5;
    const int lane = threadIdx.x & 31;
    const int q  = wid & (Ss - 1);
    const int bp = wid / Ss;              // 0..31
    const int b = bp >> 4, p = bp & 15;
    const int s0 = g_seg[b * Pp + p];
    const int e0 = (p == Pp - 1) ? Ss : g_seg[b * Pp + p + 1];
    const float* row = g_sc + ((long)b * Ss + q) * Ss;
    float mx = -1e30f;
    for (int k = s0 + lane; k < e0; k += 32) mx = fmaxf(mx, row[k]);
    #pragma unroll
    for (int o = 16; o; o >>= 1) mx = fmaxf(mx, __shfl_xor_sync(0xffffffffu, mx, o));
    float sum = 0.f;
    for (int k = s0 + lane; k < e0; k += 32) sum += __expf(row[k] - mx);
    #pragma unroll
    for (int o = 16; o; o >>= 1) sum += __shfl_xor_sync(0xffffffffu, sum, o);
    if (lane == 0) {
        g_m[bp * Ss + q]  = mx;
        g_il[bp * Ss + q] = 1.0f / sum;
    }
}

// ---------------- output GEMM: out[bp,q,:] = prob(q, seg) @ v[seg,:] ---------
__global__ void out_gemm(float* __restrict__ out)
{
    __shared__ float As[16][65];
    __shared__ __align__(16) float Bs[16][68];
    const int bp = blockIdx.z;
    const int b = bp >> 4, p = bp & 15;
    const int s0 = g_seg[b * Pp + p];
    const int e0 = (p == Pp - 1) ? Ss : g_seg[b * Pp + p + 1];
    const int L = e0 - s0;
    const int tid = threadIdx.x;
    const int m0 = blockIdx.y * 64;
    const int n0 = blockIdx.x * 64;
    const int arow = tid >> 2, ak4 = (tid & 3) << 2;
    const int bkr  = tid >> 4, bn4 = (tid & 15) << 2;
    const int mr = (tid >> 4) << 2, nr = (tid & 15) << 2;
    const float* srow = g_sc + ((long)b * Ss + m0 + arow) * Ss + s0;
    const float  mrow = g_m[bp * Ss + m0 + arow];
    const float  ilrw = g_il[bp * Ss + m0 + arow];
    const float* vb = g_v + b * Ss * Dd;
    float acc[4][4] = {};
    for (int kt = 0; kt < L; kt += 16) {
        #pragma unroll
        for (int t = 0; t < 4; t++) {
            int kk = kt + ak4 + t;
            As[ak4 + t][arow] = (kk < L) ? __expf(srow[kk] - mrow) * ilrw : 0.f;
        }
        int kv = kt + bkr;
        if (kv < L) {
            *(float4*)&Bs[bkr][bn4] = *(const float4*)&vb[(s0 + kv) * Dd + n0 + bn4];
        } else {
            Bs[bkr][bn4 + 0] = 0.f; Bs[bkr][bn4 + 1] = 0.f;
            Bs[bkr][bn4 + 2] = 0.f; Bs[bkr][bn4 + 3] = 0.f;
        }
        __syncthreads();
        #pragma unroll
        for (int kk = 0; kk < 16; kk++) {
            float a[4], c[4];
            #pragma unroll
            for (int i = 0; i < 4; i++) a[i] = As[kk][mr + i];
            #pragma unroll
            for (int j = 0; j < 4; j++) c[j] = Bs[kk][nr + j];
            #pragma unroll
            for (int i = 0; i < 4; i++)
                #pragma unroll
                for (int j = 0; j < 4; j++) acc[i][j] += a[i] * c[j];
        }
        __syncthreads();
    }
    float* dst = out + ((long)bp * Ss + m0) * Dd;
    #pragma unroll
    for (int i = 0; i < 4; i++)
        #pragma unroll
        for (int j = 0; j < 4; j++)
            dst[(mr + i) * Dd + n0 + nr + j] = acc[i][j];
}

// ---------------- launch -----------------------------------------------------
extern "C" void kernel_launch(void* const* d_in, const int* in_sizes, int n_in,
                              void* d_out, int out_size)
{
    const float* x   = (const float*)d_in[0];
    const void* pidx = d_in[1];
    const float* Wq = (const float*)d_in[2];
    const float* bq = (const float*)d_in[3];
    const float* Wk = (const float*)d_in[4];
    const float* bk = (const float*)d_in[5];
    const float* Wv = (const float*)d_in[6];
    const float* bv = (const float*)d_in[7];
    float* out = (float*)d_out;

    float *dq, *dk, *dv;
    cudaGetSymbolAddress((void**)&dq, g_q);
    cudaGetSymbolAddress((void**)&dk, g_k);
    cudaGetSymbolAddress((void**)&dv, g_v);

    decode_idx<<<1, 1>>>(pidx);

    dim3 pg(Dd / 64, (Bb * Ss) / 64);            // 12 x 64
    proj_gemm<<<pg, 256>>>(x, Wq, bq, dq);
    proj_gemm<<<pg, 256>>>(x, Wk, bk, dk);
    proj_gemm<<<pg, 256>>>(x, Wv, bv, dv);

    dim3 sg(Ss / 64, Ss / 64, Bb);               // 32 x 32 x 2
    scores_gemm<<<sg, 256>>>();

    int nwarps = Bb * Pp * Ss;                   // 65536
    stats_kernel<<<nwarps / 8, 256>>>();

    dim3 og(Dd / 64, Ss / 64, Bb * Pp);          // 12 x 32 x 32
    out_gemm<<<og, 256>>>(out);
}

// round 4
// speedup vs baseline: 2.1556x; 2.1556x over previous
#include <cuda_runtime.h>
#include <cuda_bf16.h>
#include <mma.h>

using namespace nvcuda;

#define Bb 2
#define Ss 2048
#define Dd 768
#define Pp 16

// ---------------- scratch (device globals) -------------------------------------
__device__ __align__(256) float g_q[Bb * Ss * Dd];
__device__ __align__(256) float g_k[Bb * Ss * Dd];
__device__ __align__(256) float g_vt[Bb * Dd * Ss];          // v transposed [b][d][s]
__device__ __align__(256) float g_sc[Bb * Ss * Ss];          // fp32 scores
__device__ __align__(256) __nv_bfloat16 g_ph[(long)Bb * Ss * Ss];  // P hi
__device__ __align__(256) __nv_bfloat16 g_pl[(long)Bb * Ss * Ss];  // P lo
__device__ __align__(256) float g_wt[3][Dd * Dd];            // W^T rows: wt[n][k]
__device__ int g_seg[Bb * Pp];

// ---------------- wmma types ----------------------------------------------------
typedef wmma::fragment<wmma::matrix_a, 16, 16, 16, __nv_bfloat16, wmma::row_major> frag_a;
typedef wmma::fragment<wmma::matrix_b, 16, 16, 16, __nv_bfloat16, wmma::col_major> frag_b;
typedef wmma::fragment<wmma::accumulator, 16, 16, 16, float> frag_c;

#define TLD 24   // smem tile leading dim (bf16 elems), mult of 8

// ---------------- helpers -------------------------------------------------------
__device__ __forceinline__ void split2(float v, __nv_bfloat16& h, __nv_bfloat16& l) {
    h = __float2bfloat16(v);
    l = __float2bfloat16(v - __bfloat162float(h));
}

// stage 128x16 fp32 tile (row-major, ld=ldsrc, pre-offset to kt) -> hi/lo bf16 smem
__device__ __forceinline__ void stage_split(const float* __restrict__ src, long ldsrc,
                                            __nv_bfloat16* hi, __nv_bfloat16* lo,
                                            float scale, int tid) {
    #pragma unroll
    for (int i = 0; i < 2; i++) {
        int idx = i * 256 + tid;              // 0..511 float4s
        int r = idx >> 2, c4 = (idx & 3) << 2;
        float4 v = *(const float4*)&src[(long)r * ldsrc + c4];
        v.x *= scale; v.y *= scale; v.z *= scale; v.w *= scale;
        __nv_bfloat16 h, l;
        int base = r * TLD + c4;
        split2(v.x, h, l); hi[base + 0] = h; lo[base + 0] = l;
        split2(v.y, h, l); hi[base + 1] = h; lo[base + 1] = l;
        split2(v.z, h, l); hi[base + 2] = h; lo[base + 2] = l;
        split2(v.w, h, l); hi[base + 3] = h; lo[base + 3] = l;
    }
}

// masked fp32 stage (zero for k >= rem)
__device__ __forceinline__ void stage_split_masked(const float* __restrict__ src, long ldsrc,
                                                   int rem, __nv_bfloat16* hi, __nv_bfloat16* lo,
                                                   int tid) {
    #pragma unroll
    for (int i = 0; i < 2; i++) {
        int idx = i * 256 + tid;
        int r = idx >> 2, c4 = (idx & 3) << 2;
        const float* sr = src + (long)r * ldsrc;
        int base = r * TLD + c4;
        #pragma unroll
        for (int e = 0; e < 4; e++) {
            float v = (c4 + e < rem) ? sr[c4 + e] : 0.f;
            __nv_bfloat16 h, l;
            split2(v, h, l);
            hi[base + e] = h; lo[base + e] = l;
        }
    }
}

// masked bf16 pair copy (P operand; already split)
__device__ __forceinline__ void stage_copy_masked(const __nv_bfloat16* __restrict__ sh,
                                                  const __nv_bfloat16* __restrict__ sl,
                                                  long ldsrc, int rem,
                                                  __nv_bfloat16* hi, __nv_bfloat16* lo, int tid) {
    const __nv_bfloat16 z = __float2bfloat16(0.f);
    #pragma unroll
    for (int i = 0; i < 2; i++) {
        int idx = i * 256 + tid;
        int r = idx >> 2, c4 = (idx & 3) << 2;
        const __nv_bfloat16* rh = sh + (long)r * ldsrc;
        const __nv_bfloat16* rl = sl + (long)r * ldsrc;
        int base = r * TLD + c4;
        #pragma unroll
        for (int e = 0; e < 4; e++) {
            bool ok = (c4 + e) < rem;
            hi[base + e] = ok ? rh[c4 + e] : z;
            lo[base + e] = ok ? rl[c4 + e] : z;
        }
    }
}

// 3-term split MMA on one staged K=16 slab; warp tile 32x64 at (wm, wn)
__device__ __forceinline__ void mma_block(frag_c (&acc)[2][4],
                                          const __nv_bfloat16* Ahi, const __nv_bfloat16* Alo,
                                          const __nv_bfloat16* Bhi, const __nv_bfloat16* Blo,
                                          int wm, int wn) {
    frag_a ah[2], al[2];
    frag_b bh[4], bl[4];
    #pragma unroll
    for (int i = 0; i < 2; i++) {
        wmma::load_matrix_sync(ah[i], Ahi + (wm * 32 + i * 16) * TLD, TLD);
        wmma::load_matrix_sync(al[i], Alo + (wm * 32 + i * 16) * TLD, TLD);
    }
    #pragma unroll
    for (int j = 0; j < 4; j++) {
        wmma::load_matrix_sync(bh[j], Bhi + (wn * 64 + j * 16) * TLD, TLD);
        wmma::load_matrix_sync(bl[j], Blo + (wn * 64 + j * 16) * TLD, TLD);
    }
    #pragma unroll
    for (int i = 0; i < 2; i++)
        #pragma unroll
        for (int j = 0; j < 4; j++) {
            wmma::mma_sync(acc[i][j], ah[i], bh[j], acc[i][j]);
            wmma::mma_sync(acc[i][j], ah[i], bl[j], acc[i][j]);
            wmma::mma_sync(acc[i][j], al[i], bh[j], acc[i][j]);
        }
}

// ---------------- decode patch indices (robust to int32/int64) ------------------
__global__ void decode_idx(const void* __restrict__ raw) {
    const long long* p64 = (const long long*)raw;
    const int* p32 = (const int*)raw;
    bool ok64 = true;
    for (int b = 0; b < Bb && ok64; b++) {
        long long prev = -1;
        for (int p = 0; p < Pp; p++) {
            long long v = p64[b * Pp + p];
            if (v < 0 || v >= Ss || v <= prev) { ok64 = false; break; }
            prev = v;
        }
    }
    for (int i = 0; i < Bb * Pp; i++)
        g_seg[i] = ok64 ? (int)p64[i] : p32[i];
}

// ---------------- W transpose ----------------------------------------------------
__global__ void transpose_w(const float* __restrict__ Wq, const float* __restrict__ Wk,
                            const float* __restrict__ Wv) {
    __shared__ float t[32][33];
    int z = blockIdx.z;
    const float* W = (z == 0) ? Wq : (z == 1) ? Wk : Wv;
    int x0 = blockIdx.x * 32, y0 = blockIdx.y * 32;
    int tx = threadIdx.x, ty = threadIdx.y;  // 32x8
    #pragma unroll
    for (int i = 0; i < 32; i += 8) t[ty + i][tx] = W[(y0 + ty + i) * Dd + x0 + tx];
    __syncthreads();
    #pragma unroll
    for (int i = 0; i < 32; i += 8) g_wt[z][(x0 + ty + i) * Dd + y0 + tx] = t[tx][ty + i];
}

// ---------------- projection: q/k row-major; v transposed; +bias -----------------
__global__ void __launch_bounds__(256) proj_tc(const float* __restrict__ x,
                                               const float* __restrict__ b0,
                                               const float* __restrict__ b1,
                                               const float* __restrict__ b2) {
    __shared__ __nv_bfloat16 sAhi[128 * TLD], sAlo[128 * TLD];
    __shared__ __nv_bfloat16 sBhi[128 * TLD], sBlo[128 * TLD];
    __shared__ float bounce[8][16 * 20];
    const int tid = threadIdx.x, warp = tid >> 5, lane = tid & 31;
    const int wm = warp >> 1, wn = warp & 1;
    const int z = blockIdx.z;
    const int n0 = blockIdx.x * 128, m0 = blockIdx.y * 128;

    const float* Asrc = x + (long)m0 * Dd;
    const float* Bsrc = g_wt[z] + (long)n0 * Dd;

    frag_c acc[2][4];
    #pragma unroll
    for (int i = 0; i < 2; i++)
        #pragma unroll
        for (int j = 0; j < 4; j++) wmma::fill_fragment(acc[i][j], 0.f);

    for (int kt = 0; kt < Dd; kt += 16) {
        __syncthreads();
        stage_split(Asrc + kt, Dd, sAhi, sAlo, 1.f, tid);
        stage_split(Bsrc + kt, Dd, sBhi, sBlo, 1.f, tid);
        __syncthreads();
        mma_block(acc, sAhi, sAlo, sBhi, sBlo, wm, wn);
    }

    const float* bias = (z == 0) ? b0 : (z == 1) ? b1 : b2;
    #pragma unroll
    for (int i = 0; i < 2; i++)
        #pragma unroll
        for (int j = 0; j < 4; j++) {
            wmma::store_matrix_sync(bounce[warp], acc[i][j], 20, wmma::mem_row_major);
            __syncwarp();
            int gm = m0 + wm * 32 + i * 16;
            int gn = n0 + wn * 64 + j * 16;
            if (z == 2) {
                // vt[(b*Dd + d)*Ss + s], block fully inside one batch
                int b = m0 >> 11;
                int sbase = (m0 & (Ss - 1)) + wm * 32 + i * 16;
                int c = lane >> 1;               // d col 0..15
                int rs = (lane & 1) * 8;         // 8 rows
                float bi = bias[gn + c];
                #pragma unroll
                for (int t = 0; t < 8; t++)
                    g_vt[((long)b * Dd + gn + c) * Ss + sbase + rs + t] =
                        bounce[warp][(rs + t) * 20 + c] + bi;
            } else {
                float* dst = (z == 0) ? g_q : g_k;
                int r = lane >> 1, cs = (lane & 1) * 8;
                #pragma unroll
                for (int t = 0; t < 8; t++)
                    dst[(long)(gm + r) * Dd + gn + cs + t] =
                        bounce[warp][r * 20 + cs + t] + bias[gn + cs + t];
            }
            __syncwarp();
        }
}

// ---------------- scores: sc = (q*scale) @ k^T -----------------------------------
__global__ void __launch_bounds__(256) scores_tc() {
    __shared__ __nv_bfloat16 sAhi[128 * TLD], sAlo[128 * TLD];
    __shared__ __nv_bfloat16 sBhi[128 * TLD], sBlo[128 * TLD];
    const int tid = threadIdx.x, warp = tid >> 5;
    const int wm = warp >> 1, wn = warp & 1;
    const int b = blockIdx.z;
    const int n0 = blockIdx.x * 128, m0 = blockIdx.y * 128;
    const float scale = 0.03608439182435161f;  // 1/sqrt(768)

    const float* Asrc = g_q + ((long)b * Ss + m0) * Dd;
    const float* Bsrc = g_k + ((long)b * Ss + n0) * Dd;

    frag_c acc[2][4];
    #pragma unroll
    for (int i = 0; i < 2; i++)
        #pragma unroll
        for (int j = 0; j < 4; j++) wmma::fill_fragment(acc[i][j], 0.f);

    for (int kt = 0; kt < Dd; kt += 16) {
        __syncthreads();
        stage_split(Asrc + kt, Dd, sAhi, sAlo, scale, tid);
        stage_split(Bsrc + kt, Dd, sBhi, sBlo, 1.f, tid);
        __syncthreads();
        mma_block(acc, sAhi, sAlo, sBhi, sBlo, wm, wn);
    }

    float* dst = g_sc + (long)b * Ss * Ss;
    #pragma unroll
    for (int i = 0; i < 2; i++)
        #pragma unroll
        for (int j = 0; j < 4; j++) {
            int gm = m0 + wm * 32 + i * 16;
            int gn = n0 + wn * 64 + j * 16;
            wmma::store_matrix_sync(&dst[(long)gm * Ss + gn], acc[i][j], Ss,
                                    wmma::mem_row_major);
        }
}

// ---------------- softmax stats + P (bf16 hi/lo) ---------------------------------
__global__ void stats_kernel() {
    const int wid = (blockIdx.x * blockDim.x + threadIdx.x) >> 5;
    const int lane = threadIdx.x & 31;
    const int q = wid & (Ss - 1);
    const int bp = wid / Ss;
    const int b = bp >> 4, p = bp & 15;
    const int s0 = g_seg[b * Pp + p];
    const int e0 = (p == Pp - 1) ? Ss : g_seg[b * Pp + p + 1];
    const long base = ((long)b * Ss + q) * Ss;
    const float* row = g_sc + base;
    float mx = -1e30f;
    for (int k = s0 + lane; k < e0; k += 32) mx = fmaxf(mx, row[k]);
    #pragma unroll
    for (int o = 16; o; o >>= 1) mx = fmaxf(mx, __shfl_xor_sync(0xffffffffu, mx, o));
    float sum = 0.f;
    for (int k = s0 + lane; k < e0; k += 32) sum += __expf(row[k] - mx);
    #pragma unroll
    for (int o = 16; o; o >>= 1) sum += __shfl_xor_sync(0xffffffffu, sum, o);
    float inv = 1.0f / sum;
    for (int k = s0 + lane; k < e0; k += 32) {
        float pv = __expf(row[k] - mx) * inv;
        __nv_bfloat16 h, l;
        split2(pv, h, l);
        g_ph[base + k] = h;
        g_pl[base + k] = l;
    }
}

// ---------------- output: out[bp] = P @ V (V pre-transposed) ---------------------
__global__ void __launch_bounds__(256) out_tc(float* __restrict__ out) {
    __shared__ __nv_bfloat16 sAhi[128 * TLD], sAlo[128 * TLD];
    __shared__ __nv_bfloat16 sBhi[128 * TLD], sBlo[128 * TLD];
    const int tid = threadIdx.x, warp = tid >> 5;
    const int wm = warp >> 1, wn = warp & 1;
    const int bp = blockIdx.z;
    const int b = bp >> 4, p = bp & 15;
    const int s0 = g_seg[b * Pp + p];
    const int e0 = (p == Pp - 1) ? Ss : g_seg[b * Pp + p + 1];
    const int L = e0 - s0;
    const int NC = (L + 15) >> 4;
    const int n0 = blockIdx.x * 128, m0 = blockIdx.y * 128;

    const __nv_bfloat16* Ph = g_ph + ((long)b * Ss + m0) * Ss + s0;
    const __nv_bfloat16* Pl = g_pl + ((long)b * Ss + m0) * Ss + s0;
    const float* Vt = g_vt + ((long)b * Dd + n0) * Ss + s0;

    frag_c acc[2][4];
    #pragma unroll
    for (int i = 0; i < 2; i++)
        #pragma unroll
        for (int j = 0; j < 4; j++) wmma::fill_fragment(acc[i][j], 0.f);

    for (int c = 0; c < NC; c++) {
        int kt = c * 16;
        int rem = L - kt;
        __syncthreads();
        stage_copy_masked(Ph + kt, Pl + kt, Ss, rem, sAhi, sAlo, tid);
        stage_split_masked(Vt + kt, Ss, rem, sBhi, sBlo, tid);
        __syncthreads();
        mma_block(acc, sAhi, sAlo, sBhi, sBlo, wm, wn);
    }

    float* dst = out + ((long)bp * Ss + m0) * Dd;
    #pragma unroll
    for (int i = 0; i < 2; i++)
        #pragma unroll
        for (int j = 0; j < 4; j++) {
            int rm = wm * 32 + i * 16;
            int gn = n0 + wn * 64 + j * 16;
            wmma::store_matrix_sync(&dst[(long)rm * Dd + gn], acc[i][j], Dd,
                                    wmma::mem_row_major);
        }
}

// ---------------- launch ----------------------------------------------------------
extern "C" void kernel_launch(void* const* d_in, const int* in_sizes, int n_in,
                              void* d_out, int out_size) {
    const float* x = (const float*)d_in[0];
    const void* pidx = d_in[1];
    const float* Wq = (const float*)d_in[2];
    const float* bq = (const float*)d_in[3];
    const float* Wk = (const float*)d_in[4];
    const float* bk = (const float*)d_in[5];
    const float* Wv = (const float*)d_in[6];
    const float* bv = (const float*)d_in[7];
    float* out = (float*)d_out;

    decode_idx<<<1, 1>>>(pidx);

    dim3 tg(Dd / 32, Dd / 32, 3);
    transpose_w<<<tg, dim3(32, 8)>>>(Wq, Wk, Wv);

    dim3 pg(Dd / 128, (Bb * Ss) / 128, 3);           // 6 x 32 x 3
    proj_tc<<<pg, 256>>>(x, bq, bk, bv);

    dim3 sg(Ss / 128, Ss / 128, Bb);                 // 16 x 16 x 2
    scores_tc<<<sg, 256>>>();

    stats_kernel<<<(Bb * Pp * Ss) / 8, 256>>>();

    dim3 og(Dd / 128, Ss / 128, Bb * Pp);            // 6 x 16 x 32
    out_tc<<<og, 256>>>(out);
}

// round 5
// speedup vs baseline: 2.4547x; 1.1387x over previous
#include <cuda_runtime.h>
#include <cuda_bf16.h>
#include <mma.h>

using namespace nvcuda;

#define Bb 2
#define Ss 2048
#define Dd 768
#define Pp 16
#define SCALE 0.03608439182435161f   // 1/sqrt(768)

#define PSEG (Bb * Ss * (Ss + Pp * 32))   // padded P elems
#define VSEG (Bb * Dd * (Ss + Pp * 32))   // padded V elems

// ---------------- scratch (device globals) -------------------------------------
__device__ __align__(256) float g_sc[Bb * Ss * Ss];
__device__ __align__(256) __nv_bfloat16 g_xh[Bb * Ss * Dd], g_xl[Bb * Ss * Dd];
__device__ __align__(256) __nv_bfloat16 g_wth[3 * Dd * Dd], g_wtl[3 * Dd * Dd];
__device__ __align__(256) __nv_bfloat16 g_qh[Bb * Ss * Dd], g_ql[Bb * Ss * Dd];
__device__ __align__(256) __nv_bfloat16 g_kh[Bb * Ss * Dd], g_kl[Bb * Ss * Dd];
__device__ __align__(256) __nv_bfloat16 g_ph[PSEG], g_pl[PSEG];
__device__ __align__(256) __nv_bfloat16 g_vh[VSEG], g_vl[VSEG];
__device__ int g_seg[Bb * Pp];
__device__ int g_Lp[Bb * Pp];
__device__ long long g_poff[Bb * Pp];
__device__ long long g_voff[Bb * Pp];
__device__ int g_sp[Bb * Ss];

// ---------------- wmma types ----------------------------------------------------
typedef wmma::fragment<wmma::matrix_a, 16, 16, 16, __nv_bfloat16, wmma::row_major> frag_a;
typedef wmma::fragment<wmma::matrix_b, 16, 16, 16, __nv_bfloat16, wmma::col_major> frag_b;
typedef wmma::fragment<wmma::accumulator, 16, 16, 16, float> frag_c;

#define TLD 40                       // smem tile ld (bf16): 80B rows, 16B-aligned
#define TILE_B 10240                 // one 128xTLD bf16 tile
#define STAGE_B 40960                // 4 tiles
#define SMEM_BYTES 81920             // 2 stages

// ---------------- helpers -------------------------------------------------------
__device__ __forceinline__ unsigned smem_u32(const void* p) {
    unsigned a;
    asm("{ .reg .u64 t; cvta.to.shared.u64 t, %1; cvt.u32.u64 %0, t; }" : "=r"(a) : "l"(p));
    return a;
}
#define CP16(daddr, gptr) \
    asm volatile("cp.async.cg.shared.global [%0], [%1], 16;" :: "r"(daddr), "l"(gptr) : "memory")
__device__ __forceinline__ void cp_commit() { asm volatile("cp.async.commit_group;" ::: "memory"); }
__device__ __forceinline__ void cp_wait0() { asm volatile("cp.async.wait_group 0;" ::: "memory"); }
__device__ __forceinline__ void cp_wait1() { asm volatile("cp.async.wait_group 1;" ::: "memory"); }

__device__ __forceinline__ void split2(float v, __nv_bfloat16& h, __nv_bfloat16& l) {
    h = __float2bfloat16(v);
    l = __float2bfloat16(v - __bfloat162float(h));
}

// stage one K=32 chunk: 4 tiles (Ahi/Alo/Bhi/Blo), pure 16B async copies
__device__ __forceinline__ void stage4(const __nv_bfloat16* Ah, const __nv_bfloat16* Al, long lda,
                                       const __nv_bfloat16* Bh, const __nv_bfloat16* Bl, long ldb,
                                       unsigned sb, int tid) {
    #pragma unroll
    for (int i = 0; i < 2; i++) {
        int ch = i * 256 + tid;              // 0..511
        int r = ch >> 2, c = (ch & 3) << 3;  // row, elem col (0/8/16/24)
        unsigned so = (unsigned)(r * 80 + c * 2);
        CP16(sb + so, Ah + (long)r * lda + c);
        CP16(sb + TILE_B + so, Al + (long)r * lda + c);
        CP16(sb + 2 * TILE_B + so, Bh + (long)r * ldb + c);
        CP16(sb + 3 * TILE_B + so, Bl + (long)r * ldb + c);
    }
}

// 3-term split MMA over one staged K=32 chunk; warp tile 32x64 at (wm, wn)
__device__ __forceinline__ void mma_chunk(frag_c (&acc)[2][4], const char* buf, int wm, int wn) {
    const __nv_bfloat16* sAh = (const __nv_bfloat16*)buf;
    const __nv_bfloat16* sAl = (const __nv_bfloat16*)(buf + TILE_B);
    const __nv_bfloat16* sBh = (const __nv_bfloat16*)(buf + 2 * TILE_B);
    const __nv_bfloat16* sBl = (const __nv_bfloat16*)(buf + 3 * TILE_B);
    #pragma unroll
    for (int ks = 0; ks < 2; ks++) {
        frag_a ah[2], al[2];
        frag_b bh[4], bl[4];
        #pragma unroll
        for (int i = 0; i < 2; i++) {
            wmma::load_matrix_sync(ah[i], sAh + (wm * 32 + i * 16) * TLD + ks * 16, TLD);
            wmma::load_matrix_sync(al[i], sAl + (wm * 32 + i * 16) * TLD + ks * 16, TLD);
        }
        #pragma unroll
        for (int j = 0; j < 4; j++) {
            wmma::load_matrix_sync(bh[j], sBh + (wn * 64 + j * 16) * TLD + ks * 16, TLD);
            wmma::load_matrix_sync(bl[j], sBl + (wn * 64 + j * 16) * TLD + ks * 16, TLD);
        }
        #pragma unroll
        for (int i = 0; i < 2; i++)
            #pragma unroll
            for (int j = 0; j < 4; j++) {
                wmma::mma_sync(acc[i][j], ah[i], bh[j], acc[i][j]);
                wmma::mma_sync(acc[i][j], ah[i], bl[j], acc[i][j]);
                wmma::mma_sync(acc[i][j], al[i], bh[j], acc[i][j]);
            }
    }
}

// ---------------- decode + layout metadata --------------------------------------
__global__ void decode_idx(const void* __restrict__ raw) {
    const long long* p64 = (const long long*)raw;
    const int* p32 = (const int*)raw;
    bool ok64 = true;
    for (int b = 0; b < Bb && ok64; b++) {
        long long prev = -1;
        for (int p = 0; p < Pp; p++) {
            long long v = p64[b * Pp + p];
            if (v < 0 || v >= Ss || v <= prev) { ok64 = false; break; }
            prev = v;
        }
    }
    for (int i = 0; i < Bb * Pp; i++)
        g_seg[i] = ok64 ? (int)p64[i] : p32[i];
    long long po = 0, vo = 0;
    for (int bp = 0; bp < Bb * Pp; bp++) {
        int p = bp & 15;
        int s0 = g_seg[bp];
        int e0 = (p == Pp - 1) ? Ss : g_seg[bp + 1];
        int Lp = ((e0 - s0) + 31) & ~31;
        g_Lp[bp] = Lp;
        g_poff[bp] = po;
        g_voff[bp] = vo;
        po += (long long)Ss * Lp;
        vo += (long long)Dd * Lp;
    }
}

__global__ void sp_map() {
    int i = blockIdx.x * blockDim.x + threadIdx.x;   // 0..4095
    if (i >= Bb * Ss) return;
    int b = i >> 11, s = i & (Ss - 1);
    int p = -1;
    #pragma unroll
    for (int j = 0; j < Pp; j++)
        if (s >= g_seg[b * Pp + j]) p = j;
    g_sp[i] = p;
}

__global__ void zero_vpad() {
    int bp = blockIdx.x;
    int p = bp & 15;
    int s0 = g_seg[bp];
    int e0 = (p == Pp - 1) ? Ss : g_seg[bp + 1];
    int L = e0 - s0, Lp = g_Lp[bp], pad = Lp - L;
    if (pad == 0) return;
    long long off = g_voff[bp];
    __nv_bfloat16 z = __float2bfloat16(0.f);
    for (int i = threadIdx.x; i < Dd * pad; i += blockDim.x) {
        int d = i / pad, k = L + i % pad;
        long long dst = off + (long long)d * Lp + k;
        g_vh[dst] = z;
        g_vl[dst] = z;
    }
}

// ---------------- pre-split inputs ----------------------------------------------
__global__ void split_x(const float* __restrict__ x) {
    long i = (long)blockIdx.x * 256 + threadIdx.x;   // float4 index
    float4 v = ((const float4*)x)[i];
    __nv_bfloat16 h[4], l[4];
    split2(v.x, h[0], l[0]); split2(v.y, h[1], l[1]);
    split2(v.z, h[2], l[2]); split2(v.w, h[3], l[3]);
    *(uint2*)&g_xh[i * 4] = *(uint2*)h;
    *(uint2*)&g_xl[i * 4] = *(uint2*)l;
}

__global__ void transpose_w(const float* __restrict__ Wq, const float* __restrict__ Wk,
                            const float* __restrict__ Wv) {
    __shared__ float t[32][33];
    int z = blockIdx.z;
    const float* W = (z == 0) ? Wq : (z == 1) ? Wk : Wv;
    int x0 = blockIdx.x * 32, y0 = blockIdx.y * 32;
    int tx = threadIdx.x, ty = threadIdx.y;          // 32x8
    #pragma unroll
    for (int i = 0; i < 32; i += 8) t[ty + i][tx] = W[(y0 + ty + i) * Dd + x0 + tx];
    __syncthreads();
    #pragma unroll
    for (int i = 0; i < 32; i += 8) {
        float v = t[tx][ty + i];
        __nv_bfloat16 h, l;
        split2(v, h, l);
        long dst = (long)z * Dd * Dd + (long)(x0 + ty + i) * Dd + y0 + tx;
        g_wth[dst] = h;
        g_wtl[dst] = l;
    }
}

// ---------------- projection GEMM (x @ W^T-rows) ---------------------------------
__global__ void __launch_bounds__(256) proj_tc(const float* __restrict__ b0,
                                               const float* __restrict__ b1,
                                               const float* __restrict__ b2) {
    extern __shared__ char smx[];
    unsigned sbu = smem_u32(smx);
    const int tid = threadIdx.x, warp = tid >> 5, lane = tid & 31;
    const int wm = warp >> 1, wn = warp & 1;
    const int z = blockIdx.z;
    const int n0 = blockIdx.x * 128, m0 = blockIdx.y * 128;

    const __nv_bfloat16* Ah = g_xh + (long)m0 * Dd;
    const __nv_bfloat16* Al = g_xl + (long)m0 * Dd;
    const __nv_bfloat16* Bh = g_wth + (long)z * Dd * Dd + (long)n0 * Dd;
    const __nv_bfloat16* Bl = g_wtl + (long)z * Dd * Dd + (long)n0 * Dd;

    frag_c acc[2][4];
    #pragma unroll
    for (int i = 0; i < 2; i++)
        #pragma unroll
        for (int j = 0; j < 4; j++) wmma::fill_fragment(acc[i][j], 0.f);

    const int NC = Dd / 32;
    stage4(Ah, Al, Dd, Bh, Bl, Dd, sbu, tid);
    cp_commit();
    for (int c = 0; c < NC; c++) {
        if (c + 1 < NC) {
            int k = (c + 1) * 32;
            stage4(Ah + k, Al + k, Dd, Bh + k, Bl + k, Dd, sbu + ((c + 1) & 1) * STAGE_B, tid);
            cp_commit();
            cp_wait1();
        } else cp_wait0();
        __syncthreads();
        mma_chunk(acc, smx + (c & 1) * STAGE_B, wm, wn);
        __syncthreads();
    }

    const float* bias = (z == 0) ? b0 : (z == 1) ? b1 : b2;
    float* bounce = (float*)smx + warp * 320;        // 16x20
    #pragma unroll
    for (int i = 0; i < 2; i++)
        #pragma unroll
        for (int j = 0; j < 4; j++) {
            wmma::store_matrix_sync(bounce, acc[i][j], 20, wmma::mem_row_major);
            __syncwarp();
            int gm = m0 + wm * 32 + i * 16;
            int gn = n0 + wn * 64 + j * 16;
            if (z == 2) {
                int c = lane >> 1, rs = (lane & 1) * 8;
                int d = gn + c;
                float bi = bias[d];
                int bb = m0 >> 11;
                int sbase = (m0 & (Ss - 1)) + wm * 32 + i * 16 + rs;
                #pragma unroll
                for (int t = 0; t < 8; t++) {
                    int s = sbase + t;
                    int p = g_sp[bb * Ss + s];
                    if (p >= 0) {
                        int bpi = bb * Pp + p;
                        long long dst = g_voff[bpi] + (long long)d * g_Lp[bpi]
                                        + (s - g_seg[bpi]);
                        __nv_bfloat16 h, l;
                        split2(bounce[(rs + t) * 20 + c] + bi, h, l);
                        g_vh[dst] = h;
                        g_vl[dst] = l;
                    }
                }
            } else {
                int r = lane >> 1, cs = (lane & 1) * 8;
                __nv_bfloat16 hh[8], ll[8];
                #pragma unroll
                for (int t = 0; t < 8; t++) {
                    float val = bounce[r * 20 + cs + t] + bias[gn + cs + t];
                    if (z == 0) val *= SCALE;
                    split2(val, hh[t], ll[t]);
                }
                long dst = (long)(gm + r) * Dd + gn + cs;
                if (z == 0) {
                    *(uint4*)&g_qh[dst] = *(uint4*)hh;
                    *(uint4*)&g_ql[dst] = *(uint4*)ll;
                } else {
                    *(uint4*)&g_kh[dst] = *(uint4*)hh;
                    *(uint4*)&g_kl[dst] = *(uint4*)ll;
                }
            }
            __syncwarp();
        }
}

// ---------------- scores GEMM: sc = (q*scale) @ k^T ------------------------------
__global__ void __launch_bounds__(256) scores_tc() {
    extern __shared__ char smx[];
    unsigned sbu = smem_u32(smx);
    const int tid = threadIdx.x, warp = tid >> 5;
    const int wm = warp >> 1, wn = warp & 1;
    const int b = blockIdx.z;
    const int n0 = blockIdx.x * 128, m0 = blockIdx.y * 128;

    const __nv_bfloat16* Ah = g_qh + ((long)b * Ss + m0) * Dd;
    const __nv_bfloat16* Al = g_ql + ((long)b * Ss + m0) * Dd;
    const __nv_bfloat16* Bh = g_kh + ((long)b * Ss + n0) * Dd;
    const __nv_bfloat16* Bl = g_kl + ((long)b * Ss + n0) * Dd;

    frag_c acc[2][4];
    #pragma unroll
    for (int i = 0; i < 2; i++)
        #pragma unroll
        for (int j = 0; j < 4; j++) wmma::fill_fragment(acc[i][j], 0.f);

    const int NC = Dd / 32;
    stage4(Ah, Al, Dd, Bh, Bl, Dd, sbu, tid);
    cp_commit();
    for (int c = 0; c < NC; c++) {
        if (c + 1 < NC) {
            int k = (c + 1) * 32;
            stage4(Ah + k, Al + k, Dd, Bh + k, Bl + k, Dd, sbu + ((c + 1) & 1) * STAGE_B, tid);
            cp_commit();
            cp_wait1();
        } else cp_wait0();
        __syncthreads();
        mma_chunk(acc, smx + (c & 1) * STAGE_B, wm, wn);
        __syncthreads();
    }

    float* dst = g_sc + (long)b * Ss * Ss;
    #pragma unroll
    for (int i = 0; i < 2; i++)
        #pragma unroll
        for (int j = 0; j < 4; j++) {
            int gm = m0 + wm * 32 + i * 16;
            int gn = n0 + wn * 64 + j * 16;
            wmma::store_matrix_sync(&dst[(long)gm * Ss + gn], acc[i][j], Ss,
                                    wmma::mem_row_major);
        }
}

// ---------------- softmax stats -> padded P (bf16 hi/lo) -------------------------
__global__ void stats_kernel() {
    const int wid = (blockIdx.x * blockDim.x + threadIdx.x) >> 5;
    const int lane = threadIdx.x & 31;
    const int q = wid & (Ss - 1);
    const int bp = wid / Ss;
    const int b = bp >> 4, p = bp & 15;
    const int s0 = g_seg[bp];
    const int e0 = (p == Pp - 1) ? Ss : g_seg[bp + 1];
    const int Lp = g_Lp[bp];
    const float* row = g_sc + ((long)b * Ss + q) * Ss;
    float mx = -1e30f;
    for (int k = s0 + lane; k < e0; k += 32) mx = fmaxf(mx, row[k]);
    #pragma unroll
    for (int o = 16; o; o >>= 1) mx = fmaxf(mx, __shfl_xor_sync(0xffffffffu, mx, o));
    float sum = 0.f;
    for (int k = s0 + lane; k < e0; k += 32) sum += __expf(row[k] - mx);
    #pragma unroll
    for (int o = 16; o; o >>= 1) sum += __shfl_xor_sync(0xffffffffu, sum, o);
    float inv = 1.0f / sum;
    long long po = g_poff[bp] + (long long)q * Lp;
    for (int k = s0 + lane; k < s0 + Lp; k += 32) {
        float pv = (k < e0) ? __expf(row[k] - mx) * inv : 0.f;
        __nv_bfloat16 h, l;
        split2(pv, h, l);
        g_ph[po + (k - s0)] = h;
        g_pl[po + (k - s0)] = l;
    }
}

// ---------------- output GEMM: out[bp] = P @ V -----------------------------------
__global__ void __launch_bounds__(256) out_tc(float* __restrict__ out) {
    extern __shared__ char smx[];
    unsigned sbu = smem_u32(smx);
    const int tid = threadIdx.x, warp = tid >> 5;
    const int wm = warp >> 1, wn = warp & 1;
    const int bp = blockIdx.z;
    const int Lp = g_Lp[bp];
    const int NC = Lp >> 5;
    const int n0 = blockIdx.x * 128, m0 = blockIdx.y * 128;

    const __nv_bfloat16* Ah = g_ph + g_poff[bp] + (long long)m0 * Lp;
    const __nv_bfloat16* Al = g_pl + g_poff[bp] + (long long)m0 * Lp;
    const __nv_bfloat16* Bh = g_vh + g_voff[bp] + (long long)n0 * Lp;
    const __nv_bfloat16* Bl = g_vl + g_voff[bp] + (long long)n0 * Lp;

    frag_c acc[2][4];
    #pragma unroll
    for (int i = 0; i < 2; i++)
        #pragma unroll
        for (int j = 0; j < 4; j++) wmma::fill_fragment(acc[i][j], 0.f);

    stage4(Ah, Al, Lp, Bh, Bl, Lp, sbu, tid);
    cp_commit();
    for (int c = 0; c < NC; c++) {
        if (c + 1 < NC) {
            int k = (c + 1) * 32;
            stage4(Ah + k, Al + k, Lp, Bh + k, Bl + k, Lp, sbu + ((c + 1) & 1) * STAGE_B, tid);
            cp_commit();
            cp_wait1();
        } else cp_wait0();
        __syncthreads();
        mma_chunk(acc, smx + (c & 1) * STAGE_B, wm, wn);
        __syncthreads();
    }

    float* dst = out + ((long)bp * Ss + m0) * Dd;
    #pragma unroll
    for (int i = 0; i < 2; i++)
        #pragma unroll
        for (int j = 0; j < 4; j++) {
            int rm = wm * 32 + i * 16;
            int gn = n0 + wn * 64 + j * 16;
            wmma::store_matrix_sync(&dst[(long)rm * Dd + gn], acc[i][j], Dd,
                                    wmma::mem_row_major);
        }
}

// ---------------- launch ----------------------------------------------------------
extern "C" void kernel_launch(void* const* d_in, const int* in_sizes, int n_in,
                              void* d_out, int out_size) {
    const float* x = (const float*)d_in[0];
    const void* pidx = d_in[1];
    const float* Wq = (const float*)d_in[2];
    const float* bq = (const float*)d_in[3];
    const float* Wk = (const float*)d_in[4];
    const float* bk = (const float*)d_in[5];
    const float* Wv = (const float*)d_in[6];
    const float* bv = (const float*)d_in[7];
    float* out = (float*)d_out;

    static int attr_done = 0;
    if (!attr_done) {
        cudaFuncSetAttribute(proj_tc, cudaFuncAttributeMaxDynamicSharedMemorySize, SMEM_BYTES);
        cudaFuncSetAttribute(scores_tc, cudaFuncAttributeMaxDynamicSharedMemorySize, SMEM_BYTES);
        cudaFuncSetAttribute(out_tc, cudaFuncAttributeMaxDynamicSharedMemorySize, SMEM_BYTES);
        attr_done = 1;
    }

    decode_idx<<<1, 1>>>(pidx);
    sp_map<<<(Bb * Ss) / 256, 256>>>();
    zero_vpad<<<Bb * Pp, 256>>>();
    split_x<<<(Bb * Ss * Dd / 4) / 256, 256>>>(x);

    dim3 tg(Dd / 32, Dd / 32, 3);
    transpose_w<<<tg, dim3(32, 8)>>>(Wq, Wk, Wv);

    dim3 pg(Dd / 128, (Bb * Ss) / 128, 3);           // 6 x 32 x 3
    proj_tc<<<pg, 256, SMEM_BYTES>>>(bq, bk, bv);

    dim3 sg(Ss / 128, Ss / 128, Bb);                 // 16 x 16 x 2
    scores_tc<<<sg, 256, SMEM_BYTES>>>();

    stats_kernel<<<(Bb * Pp * Ss) / 8, 256>>>();

    dim3 og(Dd / 128, Ss / 128, Bb * Pp);            // 6 x 16 x 32
    out_tc<<<og, 256, SMEM_BYTES>>>(out);
}

// round 6
// speedup vs baseline: 2.5457x; 1.0371x over previous
#include <cuda_runtime.h>
#include <cuda_bf16.h>
#include <mma.h>

using namespace nvcuda;

#define Bb 2
#define Ss 2048
#define Dd 768
#define Pp 16
#define SCALE 0.03608439182435161f   // 1/sqrt(768)

#define PSEG (Bb * Ss * (Ss + Pp * 32))   // padded P elems
#define VSEG (Bb * Dd * (Ss + Pp * 32))   // padded V elems

// ---------------- scratch (device globals) -------------------------------------
__device__ __align__(256) float g_sc[Bb * Ss * Ss];
__device__ __align__(256) __nv_bfloat16 g_xh[Bb * Ss * Dd], g_xl[Bb * Ss * Dd];
__device__ __align__(256) __nv_bfloat16 g_wth[3 * Dd * Dd], g_wtl[3 * Dd * Dd];
__device__ __align__(256) __nv_bfloat16 g_qh[Bb * Ss * Dd], g_ql[Bb * Ss * Dd];
__device__ __align__(256) __nv_bfloat16 g_kh[Bb * Ss * Dd], g_kl[Bb * Ss * Dd];
__device__ __align__(256) __nv_bfloat16 g_ph[PSEG], g_pl[PSEG];
__device__ __align__(256) __nv_bfloat16 g_vh[VSEG], g_vl[VSEG];
__device__ int g_seg[Bb * Pp];
__device__ int g_Lp[Bb * Pp];
__device__ long long g_poff[Bb * Pp];
__device__ long long g_voff[Bb * Pp];
__device__ int g_sp[Bb * Ss];

// ---------------- wmma types ----------------------------------------------------
typedef wmma::fragment<wmma::matrix_a, 16, 16, 16, __nv_bfloat16, wmma::row_major> frag_a;
typedef wmma::fragment<wmma::matrix_b, 16, 16, 16, __nv_bfloat16, wmma::col_major> frag_b;
typedef wmma::fragment<wmma::accumulator, 16, 16, 16, float> frag_c;

#define TLD 40                       // smem tile ld (bf16): 80B rows, 16B-aligned
#define TILE_B 10240                 // one 128xTLD bf16 tile
#define STAGE_B 40960                // 4 tiles
#define SMEM_BYTES 81920             // 2 stages

// ---------------- helpers -------------------------------------------------------
__device__ __forceinline__ unsigned smem_u32(const void* p) {
    unsigned a;
    asm("{ .reg .u64 t; cvta.to.shared.u64 t, %1; cvt.u32.u64 %0, t; }" : "=r"(a) : "l"(p));
    return a;
}
#define CP16(daddr, gptr) \
    asm volatile("cp.async.cg.shared.global [%0], [%1], 16;" :: "r"(daddr), "l"(gptr) : "memory")
__device__ __forceinline__ void cp_commit() { asm volatile("cp.async.commit_group;" ::: "memory"); }
__device__ __forceinline__ void cp_wait0() { asm volatile("cp.async.wait_group 0;" ::: "memory"); }

__device__ __forceinline__ void split2(float v, __nv_bfloat16& h, __nv_bfloat16& l) {
    h = __float2bfloat16(v);
    l = __float2bfloat16(v - __bfloat162float(h));
}

// stage one K=32 chunk: 4 tiles (Ahi/Alo/Bhi/Blo), pure 16B async copies
__device__ __forceinline__ void stage4(const __nv_bfloat16* Ah, const __nv_bfloat16* Al, long lda,
                                       const __nv_bfloat16* Bh, const __nv_bfloat16* Bl, long ldb,
                                       unsigned sb, int tid) {
    #pragma unroll
    for (int i = 0; i < 2; i++) {
        int ch = i * 256 + tid;              // 0..511
        int r = ch >> 2, c = (ch & 3) << 3;  // row, elem col (0/8/16/24)
        unsigned so = (unsigned)(r * 80 + c * 2);
        CP16(sb + so, Ah + (long)r * lda + c);
        CP16(sb + TILE_B + so, Al + (long)r * lda + c);
        CP16(sb + 2 * TILE_B + so, Bh + (long)r * ldb + c);
        CP16(sb + 3 * TILE_B + so, Bl + (long)r * ldb + c);
    }
}

// 3-term split MMA over one staged K=32 chunk; warp tile 32x64 at (wm, wn).
// Term-major issue order: 8 independent accumulators between same-acc reuses.
__device__ __forceinline__ void mma_chunk(frag_c (&acc)[2][4], const char* buf, int wm, int wn) {
    const __nv_bfloat16* sAh = (const __nv_bfloat16*)buf;
    const __nv_bfloat16* sAl = (const __nv_bfloat16*)(buf + TILE_B);
    const __nv_bfloat16* sBh = (const __nv_bfloat16*)(buf + 2 * TILE_B);
    const __nv_bfloat16* sBl = (const __nv_bfloat16*)(buf + 3 * TILE_B);
    #pragma unroll
    for (int ks = 0; ks < 2; ks++) {
        frag_a ah[2], al[2];
        frag_b bh[4], bl[4];
        #pragma unroll
        for (int i = 0; i < 2; i++) {
            wmma::load_matrix_sync(ah[i], sAh + (wm * 32 + i * 16) * TLD + ks * 16, TLD);
            wmma::load_matrix_sync(al[i], sAl + (wm * 32 + i * 16) * TLD + ks * 16, TLD);
        }
        #pragma unroll
        for (int j = 0; j < 4; j++) {
            wmma::load_matrix_sync(bh[j], sBh + (wn * 64 + j * 16) * TLD + ks * 16, TLD);
            wmma::load_matrix_sync(bl[j], sBl + (wn * 64 + j * 16) * TLD + ks * 16, TLD);
        }
        #pragma unroll
        for (int i = 0; i < 2; i++)
            #pragma unroll
            for (int j = 0; j < 4; j++)
                wmma::mma_sync(acc[i][j], ah[i], bh[j], acc[i][j]);
        #pragma unroll
        for (int i = 0; i < 2; i++)
            #pragma unroll
            for (int j = 0; j < 4; j++)
                wmma::mma_sync(acc[i][j], ah[i], bl[j], acc[i][j]);
        #pragma unroll
        for (int i = 0; i < 2; i++)
            #pragma unroll
            for (int j = 0; j < 4; j++)
                wmma::mma_sync(acc[i][j], al[i], bh[j], acc[i][j]);
    }
}

// ---------------- decode + layout metadata --------------------------------------
__global__ void decode_idx(const void* __restrict__ raw) {
    const long long* p64 = (const long long*)raw;
    const int* p32 = (const int*)raw;
    bool ok64 = true;
    for (int b = 0; b < Bb && ok64; b++) {
        long long prev = -1;
        for (int p = 0; p < Pp; p++) {
            long long v = p64[b * Pp + p];
            if (v < 0 || v >= Ss || v <= prev) { ok64 = false; break; }
            prev = v;
        }
    }
    for (int i = 0; i < Bb * Pp; i++)
        g_seg[i] = ok64 ? (int)p64[i] : p32[i];
    long long po = 0, vo = 0;
    for (int bp = 0; bp < Bb * Pp; bp++) {
        int p = bp & 15;
        int s0 = g_seg[bp];
        int e0 = (p == Pp - 1) ? Ss : g_seg[bp + 1];
        int Lp = ((e0 - s0) + 31) & ~31;
        g_Lp[bp] = Lp;
        g_poff[bp] = po;
        g_voff[bp] = vo;
        po += (long long)Ss * Lp;
        vo += (long long)Dd * Lp;
    }
}

__global__ void sp_map() {
    int i = blockIdx.x * blockDim.x + threadIdx.x;   // 0..4095
    if (i >= Bb * Ss) return;
    int b = i >> 11, s = i & (Ss - 1);
    int p = -1;
    #pragma unroll
    for (int j = 0; j < Pp; j++)
        if (s >= g_seg[b * Pp + j]) p = j;
    g_sp[i] = p;
}

__global__ void zero_vpad() {
    int bp = blockIdx.x;
    int p = bp & 15;
    int s0 = g_seg[bp];
    int e0 = (p == Pp - 1) ? Ss : g_seg[bp + 1];
    int L = e0 - s0, Lp = g_Lp[bp], pad = Lp - L;
    if (pad == 0) return;
    long long off = g_voff[bp];
    __nv_bfloat16 z = __float2bfloat16(0.f);
    for (int i = threadIdx.x; i < Dd * pad; i += blockDim.x) {
        int d = i / pad, k = L + i % pad;
        long long dst = off + (long long)d * Lp + k;
        g_vh[dst] = z;
        g_vl[dst] = z;
    }
}

// ---------------- pre-split inputs ----------------------------------------------
__global__ void split_x(const float* __restrict__ x) {
    long i = (long)blockIdx.x * 256 + threadIdx.x;   // float4 index
    float4 v = ((const float4*)x)[i];
    __nv_bfloat16 h[4], l[4];
    split2(v.x, h[0], l[0]); split2(v.y, h[1], l[1]);
    split2(v.z, h[2], l[2]); split2(v.w, h[3], l[3]);
    *(uint2*)&g_xh[i * 4] = *(uint2*)h;
    *(uint2*)&g_xl[i * 4] = *(uint2*)l;
}

__global__ void transpose_w(const float* __restrict__ Wq, const float* __restrict__ Wk,
                            const float* __restrict__ Wv) {
    __shared__ float t[32][33];
    int z = blockIdx.z;
    const float* W = (z == 0) ? Wq : (z == 1) ? Wk : Wv;
    int x0 = blockIdx.x * 32, y0 = blockIdx.y * 32;
    int tx = threadIdx.x, ty = threadIdx.y;          // 32x8
    #pragma unroll
    for (int i = 0; i < 32; i += 8) t[ty + i][tx] = W[(y0 + ty + i) * Dd + x0 + tx];
    __syncthreads();
    #pragma unroll
    for (int i = 0; i < 32; i += 8) {
        float v = t[tx][ty + i];
        __nv_bfloat16 h, l;
        split2(v, h, l);
        long dst = (long)z * Dd * Dd + (long)(x0 + ty + i) * Dd + y0 + tx;
        g_wth[dst] = h;
        g_wtl[dst] = l;
    }
}

// ---------------- projection GEMM (x @ W^T-rows) ---------------------------------
__global__ void __launch_bounds__(256) proj_tc(const float* __restrict__ b0,
                                               const float* __restrict__ b1,
                                               const float* __restrict__ b2) {
    extern __shared__ char smx[];
    unsigned sbu = smem_u32(smx);
    const int tid = threadIdx.x, warp = tid >> 5, lane = tid & 31;
    const int wm = warp >> 1, wn = warp & 1;
    const int z = blockIdx.z;
    const int n0 = blockIdx.x * 128, m0 = blockIdx.y * 128;

    const __nv_bfloat16* Ah = g_xh + (long)m0 * Dd;
    const __nv_bfloat16* Al = g_xl + (long)m0 * Dd;
    const __nv_bfloat16* Bh = g_wth + (long)z * Dd * Dd + (long)n0 * Dd;
    const __nv_bfloat16* Bl = g_wtl + (long)z * Dd * Dd + (long)n0 * Dd;

    frag_c acc[2][4];
    #pragma unroll
    for (int i = 0; i < 2; i++)
        #pragma unroll
        for (int j = 0; j < 4; j++) wmma::fill_fragment(acc[i][j], 0.f);

    const int NC = Dd / 32;
    stage4(Ah, Al, Dd, Bh, Bl, Dd, sbu, tid);
    cp_commit();
    for (int c = 0; c < NC; c++) {
        cp_wait0();
        __syncthreads();
        if (c + 1 < NC) {
            int k = (c + 1) * 32;
            stage4(Ah + k, Al + k, Dd, Bh + k, Bl + k, Dd, sbu + ((c + 1) & 1) * STAGE_B, tid);
            cp_commit();
        }
        mma_chunk(acc, smx + (c & 1) * STAGE_B, wm, wn);
    }
    __syncthreads();

    const float* bias = (z == 0) ? b0 : (z == 1) ? b1 : b2;
    float* bounce = (float*)smx + warp * 320;        // 16x20
    #pragma unroll
    for (int i = 0; i < 2; i++)
        #pragma unroll
        for (int j = 0; j < 4; j++) {
            wmma::store_matrix_sync(bounce, acc[i][j], 20, wmma::mem_row_major);
            __syncwarp();
            int gm = m0 + wm * 32 + i * 16;
            int gn = n0 + wn * 64 + j * 16;
            if (z == 2) {
                int c = lane >> 1, rs = (lane & 1) * 8;
                int d = gn + c;
                float bi = bias[d];
                int bb = m0 >> 11;
                int sbase = (m0 & (Ss - 1)) + wm * 32 + i * 16 + rs;
                #pragma unroll
                for (int t = 0; t < 8; t++) {
                    int s = sbase + t;
                    int p = g_sp[bb * Ss + s];
                    if (p >= 0) {
                        int bpi = bb * Pp + p;
                        long long dst = g_voff[bpi] + (long long)d * g_Lp[bpi]
                                        + (s - g_seg[bpi]);
                        __nv_bfloat16 h, l;
                        split2(bounce[(rs + t) * 20 + c] + bi, h, l);
                        g_vh[dst] = h;
                        g_vl[dst] = l;
                    }
                }
            } else {
                int r = lane >> 1, cs = (lane & 1) * 8;
                __nv_bfloat16 hh[8], ll[8];
                #pragma unroll
                for (int t = 0; t < 8; t++) {
                    float val = bounce[r * 20 + cs + t] + bias[gn + cs + t];
                    if (z == 0) val *= SCALE;
                    split2(val, hh[t], ll[t]);
                }
                long dst = (long)(gm + r) * Dd + gn + cs;
                if (z == 0) {
                    *(uint4*)&g_qh[dst] = *(uint4*)hh;
                    *(uint4*)&g_ql[dst] = *(uint4*)ll;
                } else {
                    *(uint4*)&g_kh[dst] = *(uint4*)hh;
                    *(uint4*)&g_kl[dst] = *(uint4*)ll;
                }
            }
            __syncwarp();
        }
}

// ---------------- scores GEMM: sc = (q*scale) @ k^T ------------------------------
__global__ void __launch_bounds__(256) scores_tc() {
    extern __shared__ char smx[];
    unsigned sbu = smem_u32(smx);
    const int tid = threadIdx.x, warp = tid >> 5;
    const int wm = warp >> 1, wn = warp & 1;
    const int b = blockIdx.z;
    const int n0 = blockIdx.x * 128, m0 = blockIdx.y * 128;

    const __nv_bfloat16* Ah = g_qh + ((long)b * Ss + m0) * Dd;
    const __nv_bfloat16* Al = g_ql + ((long)b * Ss + m0) * Dd;
    const __nv_bfloat16* Bh = g_kh + ((long)b * Ss + n0) * Dd;
    const __nv_bfloat16* Bl = g_kl + ((long)b * Ss + n0) * Dd;

    frag_c acc[2][4];
    #pragma unroll
    for (int i = 0; i < 2; i++)
        #pragma unroll
        for (int j = 0; j < 4; j++) wmma::fill_fragment(acc[i][j], 0.f);

    const int NC = Dd / 32;
    stage4(Ah, Al, Dd, Bh, Bl, Dd, sbu, tid);
    cp_commit();
    for (int c = 0; c < NC; c++) {
        cp_wait0();
        __syncthreads();
        if (c + 1 < NC) {
            int k = (c + 1) * 32;
            stage4(Ah + k, Al + k, Dd, Bh + k, Bl + k, Dd, sbu + ((c + 1) & 1) * STAGE_B, tid);
            cp_commit();
        }
        mma_chunk(acc, smx + (c & 1) * STAGE_B, wm, wn);
    }

    float* dst = g_sc + (long)b * Ss * Ss;
    #pragma unroll
    for (int i = 0; i < 2; i++)
        #pragma unroll
        for (int j = 0; j < 4; j++) {
            int gm = m0 + wm * 32 + i * 16;
            int gn = n0 + wn * 64 + j * 16;
            wmma::store_matrix_sync(&dst[(long)gm * Ss + gn], acc[i][j], Ss,
                                    wmma::mem_row_major);
        }
}

// ---------------- softmax stats -> padded P (bf16 hi/lo) -------------------------
__global__ void stats_kernel() {
    const int wid = (blockIdx.x * blockDim.x + threadIdx.x) >> 5;
    const int lane = threadIdx.x & 31;
    const int q = wid & (Ss - 1);
    const int bp = wid / Ss;
    const int b = bp >> 4, p = bp & 15;
    const int s0 = g_seg[bp];
    const int e0 = (p == Pp - 1) ? Ss : g_seg[bp + 1];
    const int Lp = g_Lp[bp];
    const float* row = g_sc + ((long)b * Ss + q) * Ss;
    float mx = -1e30f;
    for (int k = s0 + lane; k < e0; k += 32) mx = fmaxf(mx, row[k]);
    #pragma unroll
    for (int o = 16; o; o >>= 1) mx = fmaxf(mx, __shfl_xor_sync(0xffffffffu, mx, o));
    float sum = 0.f;
    for (int k = s0 + lane; k < e0; k += 32) sum += __expf(row[k] - mx);
    #pragma unroll
    for (int o = 16; o; o >>= 1) sum += __shfl_xor_sync(0xffffffffu, sum, o);
    float inv = 1.0f / sum;
    long long po = g_poff[bp] + (long long)q * Lp;
    for (int k = s0 + lane; k < s0 + Lp; k += 32) {
        float pv = (k < e0) ? __expf(row[k] - mx) * inv : 0.f;
        __nv_bfloat16 h, l;
        split2(pv, h, l);
        g_ph[po + (k - s0)] = h;
        g_pl[po + (k - s0)] = l;
    }
}

// ---------------- output GEMM: out[bp] = P @ V -----------------------------------
__global__ void __launch_bounds__(256) out_tc(float* __restrict__ out) {
    extern __shared__ char smx[];
    unsigned sbu = smem_u32(smx);
    const int tid = threadIdx.x, warp = tid >> 5;
    const int wm = warp >> 1, wn = warp & 1;
    const int bp = blockIdx.z;
    const int Lp = g_Lp[bp];
    const int NC = Lp >> 5;
    const int n0 = blockIdx.x * 128, m0 = blockIdx.y * 128;

    const __nv_bfloat16* Ah = g_ph + g_poff[bp] + (long long)m0 * Lp;
    const __nv_bfloat16* Al = g_pl + g_poff[bp] + (long long)m0 * Lp;
    const __nv_bfloat16* Bh = g_vh + g_voff[bp] + (long long)n0 * Lp;
    const __nv_bfloat16* Bl = g_vl + g_voff[bp] + (long long)n0 * Lp;

    frag_c acc[2][4];
    #pragma unroll
    for (int i = 0; i < 2; i++)
        #pragma unroll
        for (int j = 0; j < 4; j++) wmma::fill_fragment(acc[i][j], 0.f);

    stage4(Ah, Al, Lp, Bh, Bl, Lp, sbu, tid);
    cp_commit();
    for (int c = 0; c < NC; c++) {
        cp_wait0();
        __syncthreads();
        if (c + 1 < NC) {
            int k = (c + 1) * 32;
            stage4(Ah + k, Al + k, Lp, Bh + k, Bl + k, Lp, sbu + ((c + 1) & 1) * STAGE_B, tid);
            cp_commit();
        }
        mma_chunk(acc, smx + (c & 1) * STAGE_B, wm, wn);
    }

    float* dst = out + ((long)bp * Ss + m0) * Dd;
    #pragma unroll
    for (int i = 0; i < 2; i++)
        #pragma unroll
        for (int j = 0; j < 4; j++) {
            int rm = wm * 32 + i * 16;
            int gn = n0 + wn * 64 + j * 16;
            wmma::store_matrix_sync(&dst[(long)rm * Dd + gn], acc[i][j], Dd,
                                    wmma::mem_row_major);
        }
}

// ---------------- launch ----------------------------------------------------------
extern "C" void kernel_launch(void* const* d_in, const int* in_sizes, int n_in,
                              void* d_out, int out_size) {
    const float* x = (const float*)d_in[0];
    const void* pidx = d_in[1];
    const float* Wq = (const float*)d_in[2];
    const float* bq = (const float*)d_in[3];
    const float* Wk = (const float*)d_in[4];
    const float* bk = (const float*)d_in[5];
    const float* Wv = (const float*)d_in[6];
    const float* bv = (const float*)d_in[7];
    float* out = (float*)d_out;

    static int attr_done = 0;
    if (!attr_done) {
        cudaFuncSetAttribute(proj_tc, cudaFuncAttributeMaxDynamicSharedMemorySize, SMEM_BYTES);
        cudaFuncSetAttribute(scores_tc, cudaFuncAttributeMaxDynamicSharedMemorySize, SMEM_BYTES);
        cudaFuncSetAttribute(out_tc, cudaFuncAttributeMaxDynamicSharedMemorySize, SMEM_BYTES);
        attr_done = 1;
    }

    decode_idx<<<1, 1>>>(pidx);
    sp_map<<<(Bb * Ss) / 256, 256>>>();
    zero_vpad<<<Bb * Pp, 256>>>();
    split_x<<<(Bb * Ss * Dd / 4) / 256, 256>>>(x);

    dim3 tg(Dd / 32, Dd / 32, 3);
    transpose_w<<<tg, dim3(32, 8)>>>(Wq, Wk, Wv);

    dim3 pg(Dd / 128, (Bb * Ss) / 128, 3);           // 6 x 32 x 3
    proj_tc<<<pg, 256, SMEM_BYTES>>>(bq, bk, bv);

    dim3 sg(Ss / 128, Ss / 128, Bb);                 // 16 x 16 x 2
    scores_tc<<<sg, 256, SMEM_BYTES>>>();

    stats_kernel<<<(Bb * Pp * Ss) / 8, 256>>>();

    dim3 og(Dd / 128, Ss / 128, Bb * Pp);            // 6 x 16 x 32
    out_tc<<<og, 256, SMEM_BYTES>>>(out);
}

// round 7
// speedup vs baseline: 2.6281x; 1.0323x over previous
#include <cuda_runtime.h>
#include <cuda_bf16.h>
#include <mma.h>

using namespace nvcuda;

#define Bb 2
#define Ss 2048
#define Dd 768
#define Pp 16
#define SCALE 0.03608439182435161f   // 1/sqrt(768)

#define PSEG (Bb * Ss * (Ss + Pp * 32))   // padded P elems
#define VSEG (Bb * Dd * (Ss + Pp * 32))   // padded V elems

// ---------------- scratch (device globals) -------------------------------------
__device__ __align__(256) float g_sc[Bb * Ss * Ss];
__device__ __align__(256) __nv_bfloat16 g_xh[Bb * Ss * Dd], g_xl[Bb * Ss * Dd];
__device__ __align__(256) __nv_bfloat16 g_wth[3 * Dd * Dd], g_wtl[3 * Dd * Dd];
__device__ __align__(256) __nv_bfloat16 g_qh[Bb * Ss * Dd], g_ql[Bb * Ss * Dd];
__device__ __align__(256) __nv_bfloat16 g_kh[Bb * Ss * Dd], g_kl[Bb * Ss * Dd];
__device__ __align__(256) __nv_bfloat16 g_ph[PSEG], g_pl[PSEG];
__device__ __align__(256) __nv_bfloat16 g_vh[VSEG], g_vl[VSEG];
__device__ int g_seg[Bb * Pp];
__device__ int g_Lp[Bb * Pp];
__device__ long long g_poff[Bb * Pp];
__device__ long long g_voff[Bb * Pp];
__device__ int g_sp[Bb * Ss];

// ---------------- wmma types ----------------------------------------------------
typedef wmma::fragment<wmma::matrix_a, 16, 16, 16, __nv_bfloat16, wmma::row_major> frag_a;
typedef wmma::fragment<wmma::matrix_b, 16, 16, 16, __nv_bfloat16, wmma::col_major> frag_b;
typedef wmma::fragment<wmma::accumulator, 16, 16, 16, float> frag_c;

// Block tile 128(M) x 256(N), K-chunk 32. Warp tile 64x64, warps 2x4.
#define TLD 40                        // smem ld (bf16): 80B rows
#define A_TILE 10240                  // 128 x TLD x 2B
#define B_TILE 20480                  // 256 x TLD x 2B
#define STAGE_B 61440                 // Ahi+Alo+Bhi+Blo
#define SMEM_BYTES 122880             // 2 stages

// ---------------- helpers -------------------------------------------------------
__device__ __forceinline__ unsigned smem_u32(const void* p) {
    unsigned a;
    asm("{ .reg .u64 t; cvta.to.shared.u64 t, %1; cvt.u32.u64 %0, t; }" : "=r"(a) : "l"(p));
    return a;
}
#define CP16(daddr, gptr) \
    asm volatile("cp.async.cg.shared.global [%0], [%1], 16;" :: "r"(daddr), "l"(gptr) : "memory")
__device__ __forceinline__ void cp_commit() { asm volatile("cp.async.commit_group;" ::: "memory"); }
__device__ __forceinline__ void cp_wait0() { asm volatile("cp.async.wait_group 0;" ::: "memory"); }

__device__ __forceinline__ void split2(float v, __nv_bfloat16& h, __nv_bfloat16& l) {
    h = __float2bfloat16(v);
    l = __float2bfloat16(v - __bfloat162float(h));
}

// stage one K=32 chunk: A(128 rows) + B(256 rows), hi/lo, pure 16B async copies
__device__ __forceinline__ void stage_ab(const __nv_bfloat16* Ah, const __nv_bfloat16* Al, long lda,
                                         const __nv_bfloat16* Bh, const __nv_bfloat16* Bl, long ldb,
                                         unsigned sb, int tid) {
    #pragma unroll
    for (int i = 0; i < 2; i++) {
        int ch = i * 256 + tid;              // 0..511
        int r = ch >> 2, c = (ch & 3) << 3;
        unsigned so = (unsigned)(r * 80 + c * 2);
        CP16(sb + so, Ah + (long)r * lda + c);
        CP16(sb + A_TILE + so, Al + (long)r * lda + c);
    }
    #pragma unroll
    for (int i = 0; i < 4; i++) {
        int ch = i * 256 + tid;              // 0..1023
        int r = ch >> 2, c = (ch & 3) << 3;
        unsigned so = (unsigned)(r * 80 + c * 2);
        CP16(sb + 2 * A_TILE + so, Bh + (long)r * ldb + c);
        CP16(sb + 2 * A_TILE + B_TILE + so, Bl + (long)r * ldb + c);
    }
}

// 3-term split MMA over one staged K=32 chunk; warp tile 64x64 at (wm, wn)
__device__ __forceinline__ void mma_chunk(frag_c (&acc)[4][4], const char* buf, int wm, int wn) {
    const __nv_bfloat16* sAh = (const __nv_bfloat16*)buf;
    const __nv_bfloat16* sAl = (const __nv_bfloat16*)(buf + A_TILE);
    const __nv_bfloat16* sBh = (const __nv_bfloat16*)(buf + 2 * A_TILE);
    const __nv_bfloat16* sBl = (const __nv_bfloat16*)(buf + 2 * A_TILE + B_TILE);
    #pragma unroll
    for (int ks = 0; ks < 2; ks++) {
        frag_a ah[4], al[4];
        frag_b bh[4], bl[4];
        #pragma unroll
        for (int i = 0; i < 4; i++) {
            wmma::load_matrix_sync(ah[i], sAh + (wm * 64 + i * 16) * TLD + ks * 16, TLD);
            wmma::load_matrix_sync(al[i], sAl + (wm * 64 + i * 16) * TLD + ks * 16, TLD);
        }
        #pragma unroll
        for (int j = 0; j < 4; j++) {
            wmma::load_matrix_sync(bh[j], sBh + (wn * 64 + j * 16) * TLD + ks * 16, TLD);
            wmma::load_matrix_sync(bl[j], sBl + (wn * 64 + j * 16) * TLD + ks * 16, TLD);
        }
        #pragma unroll
        for (int i = 0; i < 4; i++)
            #pragma unroll
            for (int j = 0; j < 4; j++)
                wmma::mma_sync(acc[i][j], ah[i], bh[j], acc[i][j]);
        #pragma unroll
        for (int i = 0; i < 4; i++)
            #pragma unroll
            for (int j = 0; j < 4; j++)
                wmma::mma_sync(acc[i][j], ah[i], bl[j], acc[i][j]);
        #pragma unroll
        for (int i = 0; i < 4; i++)
            #pragma unroll
            for (int j = 0; j < 4; j++)
                wmma::mma_sync(acc[i][j], al[i], bh[j], acc[i][j]);
    }
}

// ---------------- decode + layout metadata --------------------------------------
__global__ void decode_idx(const void* __restrict__ raw) {
    const long long* p64 = (const long long*)raw;
    const int* p32 = (const int*)raw;
    bool ok64 = true;
    for (int b = 0; b < Bb && ok64; b++) {
        long long prev = -1;
        for (int p = 0; p < Pp; p++) {
            long long v = p64[b * Pp + p];
            if (v < 0 || v >= Ss || v <= prev) { ok64 = false; break; }
            prev = v;
        }
    }
    for (int i = 0; i < Bb * Pp; i++)
        g_seg[i] = ok64 ? (int)p64[i] : p32[i];
    long long po = 0, vo = 0;
    for (int bp = 0; bp < Bb * Pp; bp++) {
        int p = bp & 15;
        int s0 = g_seg[bp];
        int e0 = (p == Pp - 1) ? Ss : g_seg[bp + 1];
        int Lp = ((e0 - s0) + 31) & ~31;
        g_Lp[bp] = Lp;
        g_poff[bp] = po;
        g_voff[bp] = vo;
        po += (long long)Ss * Lp;
        vo += (long long)Dd * Lp;
    }
}

__global__ void sp_map() {
    int i = blockIdx.x * blockDim.x + threadIdx.x;
    if (i >= Bb * Ss) return;
    int b = i >> 11, s = i & (Ss - 1);
    int p = -1;
    #pragma unroll
    for (int j = 0; j < Pp; j++)
        if (s >= g_seg[b * Pp + j]) p = j;
    g_sp[i] = p;
}

__global__ void zero_vpad() {
    int bp = blockIdx.x;
    int p = bp & 15;
    int s0 = g_seg[bp];
    int e0 = (p == Pp - 1) ? Ss : g_seg[bp + 1];
    int L = e0 - s0, Lp = g_Lp[bp], pad = Lp - L;
    if (pad == 0) return;
    long long off = g_voff[bp];
    __nv_bfloat16 z = __float2bfloat16(0.f);
    for (int i = threadIdx.x; i < Dd * pad; i += blockDim.x) {
        int d = i / pad, k = L + i % pad;
        long long dst = off + (long long)d * Lp + k;
        g_vh[dst] = z;
        g_vl[dst] = z;
    }
}

// ---------------- pre-split inputs ----------------------------------------------
__global__ void split_x(const float* __restrict__ x) {
    long i = (long)blockIdx.x * 256 + threadIdx.x;
    float4 v = ((const float4*)x)[i];
    __nv_bfloat16 h[4], l[4];
    split2(v.x, h[0], l[0]); split2(v.y, h[1], l[1]);
    split2(v.z, h[2], l[2]); split2(v.w, h[3], l[3]);
    *(uint2*)&g_xh[i * 4] = *(uint2*)h;
    *(uint2*)&g_xl[i * 4] = *(uint2*)l;
}

__global__ void transpose_w(const float* __restrict__ Wq, const float* __restrict__ Wk,
                            const float* __restrict__ Wv) {
    __shared__ float t[32][33];
    int z = blockIdx.z;
    const float* W = (z == 0) ? Wq : (z == 1) ? Wk : Wv;
    int x0 = blockIdx.x * 32, y0 = blockIdx.y * 32;
    int tx = threadIdx.x, ty = threadIdx.y;
    #pragma unroll
    for (int i = 0; i < 32; i += 8) t[ty + i][tx] = W[(y0 + ty + i) * Dd + x0 + tx];
    __syncthreads();
    #pragma unroll
    for (int i = 0; i < 32; i += 8) {
        float v = t[tx][ty + i];
        __nv_bfloat16 h, l;
        split2(v, h, l);
        long dst = (long)z * Dd * Dd + (long)(x0 + ty + i) * Dd + y0 + tx;
        g_wth[dst] = h;
        g_wtl[dst] = l;
    }
}

// ---------------- projection GEMM (x @ W^T-rows), block 128x256 ------------------
__global__ void __launch_bounds__(256, 1) proj_tc(const float* __restrict__ b0,
                                                  const float* __restrict__ b1,
                                                  const float* __restrict__ b2) {
    extern __shared__ char smx[];
    unsigned sbu = smem_u32(smx);
    const int tid = threadIdx.x, warp = tid >> 5, lane = tid & 31;
    const int wm = warp >> 2, wn = warp & 3;
    const int z = blockIdx.z;
    const int n0 = blockIdx.x * 256, m0 = blockIdx.y * 128;

    const __nv_bfloat16* Ah = g_xh + (long)m0 * Dd;
    const __nv_bfloat16* Al = g_xl + (long)m0 * Dd;
    const __nv_bfloat16* Bh = g_wth + (long)z * Dd * Dd + (long)n0 * Dd;
    const __nv_bfloat16* Bl = g_wtl + (long)z * Dd * Dd + (long)n0 * Dd;

    frag_c acc[4][4];
    #pragma unroll
    for (int i = 0; i < 4; i++)
        #pragma unroll
        for (int j = 0; j < 4; j++) wmma::fill_fragment(acc[i][j], 0.f);

    const int NC = Dd / 32;
    stage_ab(Ah, Al, Dd, Bh, Bl, Dd, sbu, tid);
    cp_commit();
    for (int c = 0; c < NC; c++) {
        cp_wait0();
        __syncthreads();
        if (c + 1 < NC) {
            int k = (c + 1) * 32;
            stage_ab(Ah + k, Al + k, Dd, Bh + k, Bl + k, Dd, sbu + ((c + 1) & 1) * STAGE_B, tid);
            cp_commit();
        }
        mma_chunk(acc, smx + (c & 1) * STAGE_B, wm, wn);
    }
    __syncthreads();

    const float* bias = (z == 0) ? b0 : (z == 1) ? b1 : b2;
    float* bounce = (float*)smx + warp * 320;        // 16x20 per warp
    #pragma unroll
    for (int i = 0; i < 4; i++)
        #pragma unroll
        for (int j = 0; j < 4; j++) {
            wmma::store_matrix_sync(bounce, acc[i][j], 20, wmma::mem_row_major);
            __syncwarp();
            int gm = m0 + wm * 64 + i * 16;
            int gn = n0 + wn * 64 + j * 16;
            if (z == 2) {
                int c = lane >> 1, rs = (lane & 1) * 8;
                int d = gn + c;
                float bi = bias[d];
                int bb = m0 >> 11;
                int sbase = (gm & (Ss - 1)) + rs;
                #pragma unroll
                for (int t = 0; t < 8; t++) {
                    int s = sbase + t;
                    int p = g_sp[bb * Ss + s];
                    if (p >= 0) {
                        int bpi = bb * Pp + p;
                        long long dst = g_voff[bpi] + (long long)d * g_Lp[bpi]
                                        + (s - g_seg[bpi]);
                        __nv_bfloat16 h, l;
                        split2(bounce[(rs + t) * 20 + c] + bi, h, l);
                        g_vh[dst] = h;
                        g_vl[dst] = l;
                    }
                }
            } else {
                int r = lane >> 1, cs = (lane & 1) * 8;
                __nv_bfloat16 hh[8], ll[8];
                #pragma unroll
                for (int t = 0; t < 8; t++) {
                    float val = bounce[r * 20 + cs + t] + bias[gn + cs + t];
                    if (z == 0) val *= SCALE;
                    split2(val, hh[t], ll[t]);
                }
                long dst = (long)(gm + r) * Dd + gn + cs;
                if (z == 0) {
                    *(uint4*)&g_qh[dst] = *(uint4*)hh;
                    *(uint4*)&g_ql[dst] = *(uint4*)ll;
                } else {
                    *(uint4*)&g_kh[dst] = *(uint4*)hh;
                    *(uint4*)&g_kl[dst] = *(uint4*)ll;
                }
            }
            __syncwarp();
        }
}

// ---------------- scores GEMM: sc = (q*scale) @ k^T, block 128x256 ---------------
__global__ void __launch_bounds__(256, 1) scores_tc() {
    extern __shared__ char smx[];
    unsigned sbu = smem_u32(smx);
    const int tid = threadIdx.x, warp = tid >> 5;
    const int wm = warp >> 2, wn = warp & 3;
    const int b = blockIdx.z;
    const int n0 = blockIdx.x * 256, m0 = blockIdx.y * 128;

    const __nv_bfloat16* Ah = g_qh + ((long)b * Ss + m0) * Dd;
    const __nv_bfloat16* Al = g_ql + ((long)b * Ss + m0) * Dd;
    const __nv_bfloat16* Bh = g_kh + ((long)b * Ss + n0) * Dd;
    const __nv_bfloat16* Bl = g_kl + ((long)b * Ss + n0) * Dd;

    frag_c acc[4][4];
    #pragma unroll
    for (int i = 0; i < 4; i++)
        #pragma unroll
        for (int j = 0; j < 4; j++) wmma::fill_fragment(acc[i][j], 0.f);

    const int NC = Dd / 32;
    stage_ab(Ah, Al, Dd, Bh, Bl, Dd, sbu, tid);
    cp_commit();
    for (int c = 0; c < NC; c++) {
        cp_wait0();
        __syncthreads();
        if (c + 1 < NC) {
            int k = (c + 1) * 32;
            stage_ab(Ah + k, Al + k, Dd, Bh + k, Bl + k, Dd, sbu + ((c + 1) & 1) * STAGE_B, tid);
            cp_commit();
        }
        mma_chunk(acc, smx + (c & 1) * STAGE_B, wm, wn);
    }

    float* dst = g_sc + (long)b * Ss * Ss;
    #pragma unroll
    for (int i = 0; i < 4; i++)
        #pragma unroll
        for (int j = 0; j < 4; j++) {
            int gm = m0 + wm * 64 + i * 16;
            int gn = n0 + wn * 64 + j * 16;
            wmma::store_matrix_sync(&dst[(long)gm * Ss + gn], acc[i][j], Ss,
                                    wmma::mem_row_major);
        }
}

// ---------------- softmax stats -> padded P (bf16 hi/lo) -------------------------
__global__ void stats_kernel() {
    const int wid = (blockIdx.x * blockDim.x + threadIdx.x) >> 5;
    const int lane = threadIdx.x & 31;
    const int q = wid & (Ss - 1);
    const int bp = wid / Ss;
    const int b = bp >> 4, p = bp & 15;
    const int s0 = g_seg[bp];
    const int e0 = (p == Pp - 1) ? Ss : g_seg[bp + 1];
    const int Lp = g_Lp[bp];
    const float* row = g_sc + ((long)b * Ss + q) * Ss;
    float mx = -1e30f;
    for (int k = s0 + lane; k < e0; k += 32) mx = fmaxf(mx, row[k]);
    #pragma unroll
    for (int o = 16; o; o >>= 1) mx = fmaxf(mx, __shfl_xor_sync(0xffffffffu, mx, o));
    float sum = 0.f;
    for (int k = s0 + lane; k < e0; k += 32) sum += __expf(row[k] - mx);
    #pragma unroll
    for (int o = 16; o; o >>= 1) sum += __shfl_xor_sync(0xffffffffu, sum, o);
    float inv = 1.0f / sum;
    long long po = g_poff[bp] + (long long)q * Lp;
    for (int k = s0 + lane; k < s0 + Lp; k += 32) {
        float pv = (k < e0) ? __expf(row[k] - mx) * inv : 0.f;
        __nv_bfloat16 h, l;
        split2(pv, h, l);
        g_ph[po + (k - s0)] = h;
        g_pl[po + (k - s0)] = l;
    }
}

// ---------------- output GEMM: out[bp] = P @ V, block 128x256 --------------------
__global__ void __launch_bounds__(256, 1) out_tc(float* __restrict__ out) {
    extern __shared__ char smx[];
    unsigned sbu = smem_u32(smx);
    const int tid = threadIdx.x, warp = tid >> 5;
    const int wm = warp >> 2, wn = warp & 3;
    const int bp = blockIdx.z;
    const int Lp = g_Lp[bp];
    const int NC = Lp >> 5;
    const int n0 = blockIdx.x * 256, m0 = blockIdx.y * 128;

    const __nv_bfloat16* Ah = g_ph + g_poff[bp] + (long long)m0 * Lp;
    const __nv_bfloat16* Al = g_pl + g_poff[bp] + (long long)m0 * Lp;
    const __nv_bfloat16* Bh = g_vh + g_voff[bp] + (long long)n0 * Lp;
    const __nv_bfloat16* Bl = g_vl + g_voff[bp] + (long long)n0 * Lp;

    frag_c acc[4][4];
    #pragma unroll
    for (int i = 0; i < 4; i++)
        #pragma unroll
        for (int j = 0; j < 4; j++) wmma::fill_fragment(acc[i][j], 0.f);

    stage_ab(Ah, Al, Lp, Bh, Bl, Lp, sbu, tid);
    cp_commit();
    for (int c = 0; c < NC; c++) {
        cp_wait0();
        __syncthreads();
        if (c + 1 < NC) {
            int k = (c + 1) * 32;
            stage_ab(Ah + k, Al + k, Lp, Bh + k, Bl + k, Lp, sbu + ((c + 1) & 1) * STAGE_B, tid);
            cp_commit();
        }
        mma_chunk(acc, smx + (c & 1) * STAGE_B, wm, wn);
    }

    float* dst = out + ((long)bp * Ss + m0) * Dd;
    #pragma unroll
    for (int i = 0; i < 4; i++)
        #pragma unroll
        for (int j = 0; j < 4; j++) {
            int rm = wm * 64 + i * 16;
            int gn = n0 + wn * 64 + j * 16;
            wmma::store_matrix_sync(&dst[(long)rm * Dd + gn], acc[i][j], Dd,
                                    wmma::mem_row_major);
        }
}

// ---------------- launch ----------------------------------------------------------
extern "C" void kernel_launch(void* const* d_in, const int* in_sizes, int n_in,
                              void* d_out, int out_size) {
    const float* x = (const float*)d_in[0];
    const void* pidx = d_in[1];
    const float* Wq = (const float*)d_in[2];
    const float* bq = (const float*)d_in[3];
    const float* Wk = (const float*)d_in[4];
    const float* bk = (const float*)d_in[5];
    const float* Wv = (const float*)d_in[6];
    const float* bv = (const float*)d_in[7];
    float* out = (float*)d_out;

    static int attr_done = 0;
    if (!attr_done) {
        cudaFuncSetAttribute(proj_tc, cudaFuncAttributeMaxDynamicSharedMemorySize, SMEM_BYTES);
        cudaFuncSetAttribute(scores_tc, cudaFuncAttributeMaxDynamicSharedMemorySize, SMEM_BYTES);
        cudaFuncSetAttribute(out_tc, cudaFuncAttributeMaxDynamicSharedMemorySize, SMEM_BYTES);
        attr_done = 1;
    }

    decode_idx<<<1, 1>>>(pidx);
    sp_map<<<(Bb * Ss) / 256, 256>>>();
    zero_vpad<<<Bb * Pp, 256>>>();
    split_x<<<(Bb * Ss * Dd / 4) / 256, 256>>>(x);

    dim3 tg(Dd / 32, Dd / 32, 3);
    transpose_w<<<tg, dim3(32, 8)>>>(Wq, Wk, Wv);

    dim3 pg(Dd / 256, (Bb * Ss) / 128, 3);           // 3 x 32 x 3
    proj_tc<<<pg, 256, SMEM_BYTES>>>(bq, bk, bv);

    dim3 sg(Ss / 256, Ss / 128, Bb);                 // 8 x 16 x 2
    scores_tc<<<sg, 256, SMEM_BYTES>>>();

    stats_kernel<<<(Bb * Pp * Ss) / 8, 256>>>();

    dim3 og(Dd / 256, Ss / 128, Bb * Pp);            // 3 x 16 x 32
    out_tc<<<og, 256, SMEM_BYTES>>>(out);
}